// round 16
// baseline (speedup 1.0000x reference)
#include <cuda_runtime.h>
#include <cuda_bf16.h>
#include <cuda_fp16.h>
#include <cstdint>

#define NN 50000
#define EE 600000
#define HH 128
#define CAP 96
#define SLOPE 0.01f

// ---------------- scratch (static device globals; no allocation) ----------------
__device__ int   g_cnt[NN];
__device__ int   g_slots[NN * CAP];
__device__ float g_bufA[NN * HH];     // fp16 h buffers (h1raw / h2raw)
__device__ float g_bufB[NN * HH];     // h1 fp16
__device__ float g_bufC[NN * HH];     // h2 fp16
__device__ __half g_wh[6 * HH * HH];  // fp16 n-major weight images

__device__ __forceinline__ float lrelu(float x) { return x >= 0.f ? x : SLOPE * x; }

// ---------------- bucket CSR build ----------------
__global__ void fill_kernel(const int* __restrict__ src, const int* __restrict__ dst) {
    int base = (blockIdx.x * blockDim.x + threadIdx.x) * 4;
#pragma unroll
    for (int j = 0; j < 4; j++) {
        int e = base + j;
        if (e < EE) {
            int s = src[e];
            int d = dst[e];
            int pos = atomicAdd(&g_cnt[d], 1);
            if (pos < CAP) g_slots[d * CAP + pos] = s;
        }
    }
}

// ---------------- weight convert: all 6 layers, one launch, fp16 ----------------
struct WPtrs { const float* p[6]; };
__global__ void wconv_all(WPtrs W) {
    int l = blockIdx.y;
    int idx = blockIdx.x * blockDim.x + threadIdx.x;
    if (idx >= HH * HH) return;
    int n = idx >> 7;
    int k = idx & 127;
    g_wh[l * HH * HH + n * HH + k] = __float2half_rn(W.p[l][k * HH + n]);
}

// ---------------- bucket gather (warp per node, fp16 in/out, on-the-fly dinv) ----------------
// prev == nullptr: out = leaky(dinv*Sum + dinv^2*self + bias)           (h1)
// prev != nullptr: out = leaky(dinv*Sum + dinv^2*self + bias + prev)    (h2; prev already leaky)
__global__ void gather_kernel(const __half* __restrict__ h,
                              const float* __restrict__ bias,
                              const __half* __restrict__ prev,
                              __half* __restrict__ out) {
    int node = (blockIdx.x * blockDim.x + threadIdx.x) >> 5;
    int lane = threadIdx.x & 31;
    if (node >= NN) return;
    int n = g_cnt[node];
    float di = rsqrtf((float)n + 1.0f);
    if (n > CAP) n = CAP;
    const int* sl = &g_slots[node * CAP];
    float4 acc = make_float4(0.f, 0.f, 0.f, 0.f);
    int j = 0;
    for (; j + 3 < n; j += 4) {
        int s0 = sl[j], s1 = sl[j + 1], s2 = sl[j + 2], s3 = sl[j + 3];
        float w0 = rsqrtf((float)g_cnt[s0] + 1.0f);
        float w1 = rsqrtf((float)g_cnt[s1] + 1.0f);
        float w2 = rsqrtf((float)g_cnt[s2] + 1.0f);
        float w3 = rsqrtf((float)g_cnt[s3] + 1.0f);
        uint2 u0 = *(const uint2*)&h[s0 * HH + lane * 4];
        uint2 u1 = *(const uint2*)&h[s1 * HH + lane * 4];
        uint2 u2 = *(const uint2*)&h[s2 * HH + lane * 4];
        uint2 u3 = *(const uint2*)&h[s3 * HH + lane * 4];
        float2 a0 = __half22float2(*(__half2*)&u0.x), b0 = __half22float2(*(__half2*)&u0.y);
        float2 a1 = __half22float2(*(__half2*)&u1.x), b1 = __half22float2(*(__half2*)&u1.y);
        float2 a2 = __half22float2(*(__half2*)&u2.x), b2 = __half22float2(*(__half2*)&u2.y);
        float2 a3 = __half22float2(*(__half2*)&u3.x), b3 = __half22float2(*(__half2*)&u3.y);
        acc.x = fmaf(w0, a0.x, acc.x); acc.y = fmaf(w0, a0.y, acc.y);
        acc.z = fmaf(w0, b0.x, acc.z); acc.w = fmaf(w0, b0.y, acc.w);
        acc.x = fmaf(w1, a1.x, acc.x); acc.y = fmaf(w1, a1.y, acc.y);
        acc.z = fmaf(w1, b1.x, acc.z); acc.w = fmaf(w1, b1.y, acc.w);
        acc.x = fmaf(w2, a2.x, acc.x); acc.y = fmaf(w2, a2.y, acc.y);
        acc.z = fmaf(w2, b2.x, acc.z); acc.w = fmaf(w2, b2.y, acc.w);
        acc.x = fmaf(w3, a3.x, acc.x); acc.y = fmaf(w3, a3.y, acc.y);
        acc.z = fmaf(w3, b3.x, acc.z); acc.w = fmaf(w3, b3.y, acc.w);
    }
    for (; j < n; j++) {
        int s0 = sl[j];
        float w0 = rsqrtf((float)g_cnt[s0] + 1.0f);
        uint2 u0 = *(const uint2*)&h[s0 * HH + lane * 4];
        float2 a0 = __half22float2(*(__half2*)&u0.x), b0 = __half22float2(*(__half2*)&u0.y);
        acc.x = fmaf(w0, a0.x, acc.x); acc.y = fmaf(w0, a0.y, acc.y);
        acc.z = fmaf(w0, b0.x, acc.z); acc.w = fmaf(w0, b0.y, acc.w);
    }
    float d2 = di * di;
    uint2 us = *(const uint2*)&h[node * HH + lane * 4];
    float2 sa = __half22float2(*(__half2*)&us.x);
    float2 sb = __half22float2(*(__half2*)&us.y);
    float4 bv = *(const float4*)&bias[lane * 4];
    float4 r;
    r.x = fmaf(di, acc.x, fmaf(d2, sa.x, bv.x));
    r.y = fmaf(di, acc.y, fmaf(d2, sa.y, bv.y));
    r.z = fmaf(di, acc.z, fmaf(d2, sb.x, bv.z));
    r.w = fmaf(di, acc.w, fmaf(d2, sb.y, bv.w));
    if (prev) {
        uint2 up = *(const uint2*)&prev[node * HH + lane * 4];
        float2 pa = __half22float2(*(__half2*)&up.x);
        float2 pb = __half22float2(*(__half2*)&up.y);
        r.x += pa.x; r.y += pa.y; r.z += pb.x; r.w += pb.y;
    }
    r.x = lrelu(r.x); r.y = lrelu(r.y); r.z = lrelu(r.z); r.w = lrelu(r.w);
    __half2 o0 = __floats2half2_rn(r.x, r.y);
    __half2 o1 = __floats2half2_rn(r.z, r.w);
    *(uint2*)&out[node * HH + lane * 4] = make_uint2(*(uint32_t*)&o0, *(uint32_t*)&o1);
}

// ---------------- mma helpers ----------------
__device__ __forceinline__ uint32_t smem_u32(const void* p) {
    uint32_t a;
    asm("{ .reg .u64 t; cvta.to.shared.u64 t, %1; cvt.u32.u64 %0, t; }" : "=r"(a) : "l"(p));
    return a;
}
__device__ __forceinline__ void cp16(uint32_t saddr, const void* g) {
    asm volatile("cp.async.cg.shared.global [%0], [%1], 16;" :: "r"(saddr), "l"(g));
}
__device__ __forceinline__ void ldsm_x4(uint32_t r[4], uint32_t addr) {
    asm volatile("ldmatrix.sync.aligned.m8n8.x4.shared.b16 {%0,%1,%2,%3}, [%4];"
                 : "=r"(r[0]), "=r"(r[1]), "=r"(r[2]), "=r"(r[3]) : "r"(addr));
}
__device__ __forceinline__ void mma_f16(float c[4], const uint32_t a[4], uint32_t b0, uint32_t b1) {
    asm volatile(
        "mma.sync.aligned.m16n8k16.row.col.f32.f16.f16.f32 "
        "{%0,%1,%2,%3}, {%4,%5,%6,%7}, {%8,%9}, {%0,%1,%2,%3};"
        : "+f"(c[0]), "+f"(c[1]), "+f"(c[2]), "+f"(c[3])
        : "r"(a[0]), "r"(a[1]), "r"(a[2]), "r"(a[3]), "r"(b0), "r"(b1));
}
__device__ __forceinline__ uint32_t pack2h(float v0, float v1) {
    __half2 hp = __floats2half2_rn(v0, v1);
    return *(uint32_t*)&hp;
}

// ---------------- 1-term MMA pass, warp tile 16x64 ----------------
template<int AO, int WO>
__device__ __forceinline__ void mma_pass1(
    uint32_t sb, uint32_t aoff_base, uint32_t axor, int acg,
    int wn, int bn_local, int bcg, float acc[8][4]) {
#pragma unroll
    for (int ks = 0; ks < 8; ks++) {
        const int kb = ks * 32;
        uint32_t ah[4];
        uint32_t a_addr = sb + aoff_base + (uint32_t)((kb + acg) ^ axor);
        ldsm_x4(ah, a_addr + AO);
#pragma unroll
        for (int p = 0; p < 4; p++) {
            const int nrow = wn * 64 + p * 16 + bn_local;
            uint32_t b_addr = sb + (uint32_t)(nrow * 256)
                            + (uint32_t)((kb + bcg) ^ ((nrow & 7) << 4));
            uint32_t bh[4];
            ldsm_x4(bh, b_addr + WO);
            mma_f16(acc[2 * p],     ah, bh[0], bh[1]);
            mma_f16(acc[2 * p + 1], ah, bh[2], bh[3]);
        }
    }
}

#define SA_A 0
#define SW_W 16384
#define GEMM_SMEM 49152

// ---------------- conv1: A fp32 -> fp16 convert prologue ----------------
__global__ void __launch_bounds__(256, 3) conv1_gemm(
    const float* __restrict__ A,
    const uint4* __restrict__ Wt,
    __half* __restrict__ C,
    int M) {
    extern __shared__ char smem[];
    const uint32_t sb = smem_u32(smem);
    const int tid = threadIdx.x;
    const int lane = tid & 31;
    const int wid = tid >> 5;
    const int wm = wid & 3;
    const int wn = wid >> 2;
    const int blockRow = blockIdx.x * 64;

#pragma unroll
    for (int i = 0; i < 8; i++) {
        int c = tid + i * 256;
        int n = c >> 4;
        int kb = (c & 15) * 16;
        uint32_t off = (uint32_t)(n * 256) + (uint32_t)(kb ^ ((n & 7) << 4));
        cp16(sb + SW_W + off, &Wt[c]);
    }
    asm volatile("cp.async.commit_group;" ::: "memory");

#pragma unroll
    for (int i = 0; i < 8; i++) {
        int idx = tid + i * 256;
        int row = idx >> 5;
        int col = (idx & 31) * 4;
        int grow = blockRow + row;
        float4 v = make_float4(0.f, 0.f, 0.f, 0.f);
        if (grow < M) v = *(const float4*)&A[grow * HH + col];
        uint32_t h0 = pack2h(v.x, v.y);
        uint32_t h1 = pack2h(v.z, v.w);
        uint32_t off = (uint32_t)(row * 256) + (uint32_t)((col * 2) ^ ((row & 7) << 4));
        *(uint2*)(smem + SA_A + off) = make_uint2(h0, h1);
    }
    asm volatile("cp.async.wait_group 0;" ::: "memory");
    __syncthreads();

    float acc[8][4];
#pragma unroll
    for (int j = 0; j < 8; j++)
#pragma unroll
        for (int q = 0; q < 4; q++) acc[j][q] = 0.f;

    const int arow = wm * 16 + (lane & 15);
    const int acg = (lane >> 4) * 16;
    const uint32_t aoff_base = (uint32_t)(arow * 256);
    const uint32_t axor = (uint32_t)((arow & 7) << 4);
    const int bn_local = (lane & 7) + ((lane >> 4) & 1) * 8;
    const int bcg = ((lane >> 3) & 1) * 16;

    mma_pass1<SA_A, SW_W>(sb, aoff_base, axor, acg, wn, bn_local, bcg, acc);

    const int g = lane >> 2, t = lane & 3;
    int rr0 = blockRow + wm * 16 + g;
#pragma unroll
    for (int h = 0; h < 2; h++) {
        int row = rr0 + h * 8;
        if (row >= M) continue;
#pragma unroll
        for (int j = 0; j < 8; j++) {
            int col = wn * 64 + j * 8 + t * 2;
            *(__half2*)&C[row * HH + col] =
                __floats2half2_rn(acc[j][h * 2 + 0], acc[j][h * 2 + 1]);
        }
    }
}

// ---------------- conv2: A already fp16 -> pure cp.async prologue ----------------
__global__ void __launch_bounds__(256, 3) conv2_gemm(
    const __half* __restrict__ A,        // h1 fp16
    const uint4* __restrict__ Wt,
    __half* __restrict__ C,
    int M) {
    extern __shared__ char smem[];
    const uint32_t sb = smem_u32(smem);
    const int tid = threadIdx.x;
    const int lane = tid & 31;
    const int wid = tid >> 5;
    const int wm = wid & 3;
    const int wn = wid >> 2;
    const int blockRow = blockIdx.x * 64;

#pragma unroll
    for (int i = 0; i < 8; i++) {
        int c = tid + i * 256;
        int n = c >> 4;
        int kb = (c & 15) * 16;
        uint32_t off = (uint32_t)(n * 256) + (uint32_t)(kb ^ ((n & 7) << 4));
        cp16(sb + SW_W + off, &Wt[c]);
    }
#pragma unroll
    for (int i = 0; i < 4; i++) {
        int idx = tid + i * 256;
        int row = idx >> 4;
        int chunk = idx & 15;
        int grow = blockRow + row;
        uint32_t off = (uint32_t)(row * 256) + (uint32_t)((chunk * 16) ^ ((row & 7) << 4));
        if (grow < M) {
            cp16(sb + SA_A + off, &A[grow * HH + chunk * 8]);
        } else {
            *(uint4*)(smem + SA_A + off) = make_uint4(0, 0, 0, 0);
        }
    }
    asm volatile("cp.async.commit_group;" ::: "memory");
    asm volatile("cp.async.wait_group 0;" ::: "memory");
    __syncthreads();

    float acc[8][4];
#pragma unroll
    for (int j = 0; j < 8; j++)
#pragma unroll
        for (int q = 0; q < 4; q++) acc[j][q] = 0.f;

    const int arow = wm * 16 + (lane & 15);
    const int acg = (lane >> 4) * 16;
    const uint32_t aoff_base = (uint32_t)(arow * 256);
    const uint32_t axor = (uint32_t)((arow & 7) << 4);
    const int bn_local = (lane & 7) + ((lane >> 4) & 1) * 8;
    const int bcg = ((lane >> 3) & 1) * 16;

    mma_pass1<SA_A, SW_W>(sb, aoff_base, axor, acg, wn, bn_local, bcg, acc);

    const int g = lane >> 2, t = lane & 3;
    int rr0 = blockRow + wm * 16 + g;
#pragma unroll
    for (int h = 0; h < 2; h++) {
        int row = rr0 + h * 8;
        if (row >= M) continue;
#pragma unroll
        for (int j = 0; j < 8; j++) {
            int col = wn * 64 + j * 8 + t * 2;
            *(__half2*)&C[row * HH + col] =
                __floats2half2_rn(acc[j][h * 2 + 0], acc[j][h * 2 + 1]);
        }
    }
}

// ---------------- 4-layer fused MLP: fp16 A via cp.async, fp16 resid ----------------
#define G_A 0
#define G_W 16384
#define G_SMEM 49152

struct MLP4Args {
    const uint4* w[4];
    const float* b[4];
};

__global__ void __launch_bounds__(256, 3) mlp4(
    const __half* __restrict__ A,     // h2 fp16 (also the residual)
    MLP4Args args,
    const float* __restrict__ gen,
    float* __restrict__ C,
    int M) {
    extern __shared__ char smem[];
    const uint32_t sb = smem_u32(smem);
    const int tid = threadIdx.x;
    const int lane = tid & 31;
    const int wid = tid >> 5;
    const int wm = wid & 3;
    const int wn = wid >> 2;
    const int blockRow = blockIdx.x * 64;

#pragma unroll
    for (int i = 0; i < 8; i++) {
        int c = tid + i * 256;
        int n = c >> 4;
        int kb = (c & 15) * 16;
        uint32_t off = (uint32_t)(n * 256) + (uint32_t)(kb ^ ((n & 7) << 4));
        cp16(sb + G_W + off, &args.w[0][c]);
    }
#pragma unroll
    for (int i = 0; i < 4; i++) {
        int idx = tid + i * 256;
        int row = idx >> 4;
        int chunk = idx & 15;
        int grow = blockRow + row;
        uint32_t off = (uint32_t)(row * 256) + (uint32_t)((chunk * 16) ^ ((row & 7) << 4));
        if (grow < M) {
            cp16(sb + G_A + off, &A[grow * HH + chunk * 8]);
        } else {
            *(uint4*)(smem + G_A + off) = make_uint4(0, 0, 0, 0);
        }
    }
    asm volatile("cp.async.commit_group;" ::: "memory");
    asm volatile("cp.async.wait_group 0;" ::: "memory");
    __syncthreads();

    const int arow = wm * 16 + (lane & 15);
    const int acg = (lane >> 4) * 16;
    const uint32_t aoff_base = (uint32_t)(arow * 256);
    const uint32_t axor = (uint32_t)((arow & 7) << 4);
    const int bn_local = (lane & 7) + ((lane >> 4) & 1) * 8;
    const int bcg = ((lane >> 3) & 1) * 16;
    const int g = lane >> 2, t = lane & 3;

    float acc[8][4];

#pragma unroll
    for (int layer = 0; layer < 4; layer++) {
#pragma unroll
        for (int j = 0; j < 8; j++)
#pragma unroll
            for (int q = 0; q < 4; q++) acc[j][q] = 0.f;
        mma_pass1<G_A, G_W>(sb, aoff_base, axor, acg, wn, bn_local, bcg, acc);
        __syncthreads();   // all warps done reading W[layer] and A smem

        if (layer < 3) {
#pragma unroll
            for (int i = 0; i < 8; i++) {
                int c = tid + i * 256;
                int n = c >> 4;
                int kb = (c & 15) * 16;
                uint32_t off = (uint32_t)(n * 256) + (uint32_t)(kb ^ ((n & 7) << 4));
                cp16(sb + G_W + off, &args.w[layer + 1][c]);
            }
            asm volatile("cp.async.commit_group;" ::: "memory");
        }

        const float* bias = args.b[layer];
        if (layer == 3) {
#pragma unroll
            for (int h = 0; h < 2; h++) {
                int row = blockRow + wm * 16 + g + h * 8;
                if (row >= M) continue;
#pragma unroll
                for (int j = 0; j < 8; j++) {
                    int col = wn * 64 + j * 8 + t * 2;
                    float v0 = lrelu(acc[j][h * 2 + 0] + bias[col]);
                    float v1 = lrelu(acc[j][h * 2 + 1] + bias[col + 1]);
                    *(float2*)&C[row * HH + col] = make_float2(v0, v1);
                }
            }
        } else {
#pragma unroll
            for (int h = 0; h < 2; h++) {
                int lrow = wm * 16 + g + h * 8;
                int grow = blockRow + lrow;
#pragma unroll
                for (int j = 0; j < 8; j++) {
                    int col = wn * 64 + j * 8 + t * 2;
                    float v0 = acc[j][h * 2 + 0] + bias[col];
                    float v1 = acc[j][h * 2 + 1] + bias[col + 1];
                    if (layer == 1) {
                        if (grow < M) {
                            uint32_t hv = *(const uint32_t*)&A[grow * HH + col];
                            float2 rv = __half22float2(*(__half2*)&hv);
                            v0 += rv.x; v1 += rv.y;
                        }
                        v0 = lrelu(v0); v1 = lrelu(v1);
                        float2 gv = (grow < M) ? *(const float2*)&gen[grow * HH + col]
                                               : make_float2(0.f, 0.f);
                        v0 = 0.5f * v0 + 0.5f * gv.x;
                        v1 = 0.5f * v1 + 0.5f * gv.y;
                    } else {
                        v0 = lrelu(v0); v1 = lrelu(v1);
                    }
                    uint32_t off = (uint32_t)(lrow * 256)
                                 + (uint32_t)((col * 2) ^ ((lrow & 7) << 4));
                    *(uint32_t*)(smem + G_A + off) = pack2h(v0, v1);
                }
            }
            asm volatile("cp.async.wait_group 0;" ::: "memory");
            __syncthreads();
        }
    }
}

// ---------------- launch ----------------
extern "C" void kernel_launch(void* const* d_in, const int* in_sizes, int n_in,
                              void* d_out, int out_size) {
    const float* x   = (const float*)d_in[0];
    const int*   ei  = (const int*)d_in[1];
    const float* gen = (const float*)d_in[2];
    const float* Wc1 = (const float*)d_in[3];
    const float* bc1 = (const float*)d_in[4];
    const float* Wc2 = (const float*)d_in[5];
    const float* bc2 = (const float*)d_in[6];
    const float* Wm1 = (const float*)d_in[7];
    const float* bm1 = (const float*)d_in[8];
    const float* Wm2 = (const float*)d_in[9];
    const float* bm2 = (const float*)d_in[10];
    const float* Wp1 = (const float*)d_in[11];
    const float* bp1 = (const float*)d_in[12];
    const float* Wp2 = (const float*)d_in[13];
    const float* bp2 = (const float*)d_in[14];

    const int* src = ei;
    const int* dst = ei + EE;

    float *bufA, *bufB, *bufC;
    __half* wh;
    int* cntp;
    cudaGetSymbolAddress((void**)&bufA, g_bufA);
    cudaGetSymbolAddress((void**)&bufB, g_bufB);
    cudaGetSymbolAddress((void**)&bufC, g_bufC);
    cudaGetSymbolAddress((void**)&wh, g_wh);
    cudaGetSymbolAddress((void**)&cntp, g_cnt);

    static bool s_init = false;
    static cudaStream_t s_side;
    static cudaEvent_t ev_fork, ev_join;
    if (!s_init) {
        cudaStreamCreateWithFlags(&s_side, cudaStreamNonBlocking);
        cudaEventCreateWithFlags(&ev_fork, cudaEventDisableTiming);
        cudaEventCreateWithFlags(&ev_join, cudaEventDisableTiming);
        cudaFuncSetAttribute(conv1_gemm, cudaFuncAttributeMaxDynamicSharedMemorySize, GEMM_SMEM);
        cudaFuncSetAttribute(conv2_gemm, cudaFuncAttributeMaxDynamicSharedMemorySize, GEMM_SMEM);
        cudaFuncSetAttribute(mlp4, cudaFuncAttributeMaxDynamicSharedMemorySize, G_SMEM);
        s_init = true;
    }

    const int gE4 = (EE / 4 + 255) / 256;
    const int gGat = (NN * 32 + 255) / 256;   // warp per node
    const int gG = (NN + 63) / 64;            // M=64 tiles

    const uint4* w4 = (const uint4*)wh;
    const int WSTEP = HH * HH / 8;
    __half* h1raw = (__half*)bufA;   // x@Wc1 (fp16)
    __half* h1buf = (__half*)bufB;   // leaky(gcn1) fp16
    __half* h2raw = (__half*)bufA;   // h1@Wc2 reuses bufA
    __half* h2buf = (__half*)bufC;   // h2 fp16

    WPtrs wp;
    wp.p[0] = Wc1; wp.p[1] = Wc2; wp.p[2] = Wm1;
    wp.p[3] = Wm2; wp.p[4] = Wp1; wp.p[5] = Wp2;
    dim3 wgrid((HH * HH + 255) / 256, 6);

    // submission order: memset(1), wconv(2), conv1(3), fill(4,side), gather1(5) -> profiled
    cudaMemsetAsync(cntp, 0, NN * sizeof(int));
    cudaEventRecord(ev_fork, 0);

    wconv_all<<<wgrid, 256>>>(wp);
    conv1_gemm<<<gG, 256, GEMM_SMEM>>>(x, w4, h1raw, NN);

    cudaStreamWaitEvent(s_side, ev_fork, 0);
    fill_kernel<<<gE4, 256, 0, s_side>>>(src, dst);
    cudaEventRecord(ev_join, s_side);

    cudaStreamWaitEvent(0, ev_join, 0);
    gather_kernel<<<gGat, 256>>>(h1raw, bc1, nullptr, h1buf);     // h1 fp16

    conv2_gemm<<<gG, 256, GEMM_SMEM>>>(h1buf, w4 + WSTEP, h2raw, NN);
    gather_kernel<<<gGat, 256>>>(h2raw, bc2, h1buf, h2buf);       // h2 fp16

    MLP4Args ma;
    ma.w[0] = w4 + 2 * WSTEP; ma.b[0] = bm1;
    ma.w[1] = w4 + 3 * WSTEP; ma.b[1] = bm2;
    ma.w[2] = w4 + 4 * WSTEP; ma.b[2] = bp1;
    ma.w[3] = w4 + 5 * WSTEP; ma.b[3] = bp2;
    mlp4<<<gG, 256, G_SMEM>>>(h2buf, ma, gen, (float*)d_out, NN);
}

// round 17
// speedup vs baseline: 1.0723x; 1.0723x over previous
#include <cuda_runtime.h>
#include <cuda_bf16.h>
#include <cuda_fp16.h>
#include <cstdint>

#define NN 50000
#define EE 600000
#define HH 128
#define CAP 96
#define SLOPE 0.01f

// ---------------- scratch (static device globals; no allocation) ----------------
__device__ int   g_cnt[NN];
__device__ float g_dinv[NN];
__device__ int   g_slots[NN * CAP];
__device__ float g_bufA[NN * HH];     // fp16 h buffers (h1raw / h2raw_scaled)
__device__ float g_bufB[NN * HH];     // h1 fp16
__device__ float g_bufC[NN * HH];     // h2 fp16
__device__ __half g_wh[6 * HH * HH];  // fp16 n-major weight images

__device__ __forceinline__ float lrelu(float x) { return x >= 0.f ? x : SLOPE * x; }

// ---------------- bucket CSR build ----------------
__global__ void fill_kernel(const int* __restrict__ src, const int* __restrict__ dst) {
    int base = (blockIdx.x * blockDim.x + threadIdx.x) * 4;
#pragma unroll
    for (int j = 0; j < 4; j++) {
        int e = base + j;
        if (e < EE) {
            int s = src[e];
            int d = dst[e];
            int pos = atomicAdd(&g_cnt[d], 1);
            if (pos < CAP) g_slots[d * CAP + pos] = s;
        }
    }
}
__global__ void dinv_kernel() {
    int i = blockIdx.x * blockDim.x + threadIdx.x;
    if (i < NN) g_dinv[i] = rsqrtf((float)g_cnt[i] + 1.0f);
}

// ---------------- weight convert: all 6 layers, one launch, fp16 ----------------
struct WPtrs { const float* p[6]; };
__global__ void wconv_all(WPtrs W) {
    int l = blockIdx.y;
    int idx = blockIdx.x * blockDim.x + threadIdx.x;
    if (idx >= HH * HH) return;
    int n = idx >> 7;
    int k = idx & 127;
    g_wh[l * HH * HH + n * HH + k] = __float2half_rn(W.p[l][k * HH + n]);
}

// ---------------- bucket gather (warp per node, fp16 in/out) ----------------
// SCALED=false: h unscaled; per-edge weight dinv[s].  out = leaky(di*Sum + di^2*self + bias [+prev])
// SCALED=true:  h pre-scaled by dinv[row]; no per-edge weight. out = leaky(di*(Sum+self) + bias [+prev])
template<bool SCALED>
__global__ void gather_kernel(const __half* __restrict__ h,
                              const float* __restrict__ bias,
                              const __half* __restrict__ prev,
                              __half* __restrict__ out) {
    int node = (blockIdx.x * blockDim.x + threadIdx.x) >> 5;
    int lane = threadIdx.x & 31;
    if (node >= NN) return;
    int n = g_cnt[node];
    if (n > CAP) n = CAP;
    const int* sl = &g_slots[node * CAP];
    float4 acc = make_float4(0.f, 0.f, 0.f, 0.f);
    int j = 0;
    for (; j + 3 < n; j += 4) {
        int s0 = sl[j], s1 = sl[j + 1], s2 = sl[j + 2], s3 = sl[j + 3];
        uint2 u0 = *(const uint2*)&h[s0 * HH + lane * 4];
        uint2 u1 = *(const uint2*)&h[s1 * HH + lane * 4];
        uint2 u2 = *(const uint2*)&h[s2 * HH + lane * 4];
        uint2 u3 = *(const uint2*)&h[s3 * HH + lane * 4];
        float2 a0 = __half22float2(*(__half2*)&u0.x), b0 = __half22float2(*(__half2*)&u0.y);
        float2 a1 = __half22float2(*(__half2*)&u1.x), b1 = __half22float2(*(__half2*)&u1.y);
        float2 a2 = __half22float2(*(__half2*)&u2.x), b2 = __half22float2(*(__half2*)&u2.y);
        float2 a3 = __half22float2(*(__half2*)&u3.x), b3 = __half22float2(*(__half2*)&u3.y);
        if (SCALED) {
            acc.x += a0.x + a1.x + a2.x + a3.x;
            acc.y += a0.y + a1.y + a2.y + a3.y;
            acc.z += b0.x + b1.x + b2.x + b3.x;
            acc.w += b0.y + b1.y + b2.y + b3.y;
        } else {
            float w0 = g_dinv[s0], w1 = g_dinv[s1], w2 = g_dinv[s2], w3 = g_dinv[s3];
            acc.x = fmaf(w0, a0.x, acc.x); acc.y = fmaf(w0, a0.y, acc.y);
            acc.z = fmaf(w0, b0.x, acc.z); acc.w = fmaf(w0, b0.y, acc.w);
            acc.x = fmaf(w1, a1.x, acc.x); acc.y = fmaf(w1, a1.y, acc.y);
            acc.z = fmaf(w1, b1.x, acc.z); acc.w = fmaf(w1, b1.y, acc.w);
            acc.x = fmaf(w2, a2.x, acc.x); acc.y = fmaf(w2, a2.y, acc.y);
            acc.z = fmaf(w2, b2.x, acc.z); acc.w = fmaf(w2, b2.y, acc.w);
            acc.x = fmaf(w3, a3.x, acc.x); acc.y = fmaf(w3, a3.y, acc.y);
            acc.z = fmaf(w3, b3.x, acc.z); acc.w = fmaf(w3, b3.y, acc.w);
        }
    }
    for (; j < n; j++) {
        int s0 = sl[j];
        uint2 u0 = *(const uint2*)&h[s0 * HH + lane * 4];
        float2 a0 = __half22float2(*(__half2*)&u0.x), b0 = __half22float2(*(__half2*)&u0.y);
        if (SCALED) {
            acc.x += a0.x; acc.y += a0.y; acc.z += b0.x; acc.w += b0.y;
        } else {
            float w0 = g_dinv[s0];
            acc.x = fmaf(w0, a0.x, acc.x); acc.y = fmaf(w0, a0.y, acc.y);
            acc.z = fmaf(w0, b0.x, acc.z); acc.w = fmaf(w0, b0.y, acc.w);
        }
    }
    float di = g_dinv[node];
    uint2 us = *(const uint2*)&h[node * HH + lane * 4];
    float2 sa = __half22float2(*(__half2*)&us.x);
    float2 sb = __half22float2(*(__half2*)&us.y);
    float4 bv = *(const float4*)&bias[lane * 4];
    float4 r;
    if (SCALED) {
        // h already carries dinv[row]: Sum term needs *di; self = di * hscaled[node]
        r.x = fmaf(di, acc.x + sa.x, bv.x);
        r.y = fmaf(di, acc.y + sa.y, bv.y);
        r.z = fmaf(di, acc.z + sb.x, bv.z);
        r.w = fmaf(di, acc.w + sb.y, bv.w);
    } else {
        float d2 = di * di;
        r.x = fmaf(di, acc.x, fmaf(d2, sa.x, bv.x));
        r.y = fmaf(di, acc.y, fmaf(d2, sa.y, bv.y));
        r.z = fmaf(di, acc.z, fmaf(d2, sb.x, bv.z));
        r.w = fmaf(di, acc.w, fmaf(d2, sb.y, bv.w));
    }
    if (prev) {
        uint2 up = *(const uint2*)&prev[node * HH + lane * 4];
        float2 pa = __half22float2(*(__half2*)&up.x);
        float2 pb = __half22float2(*(__half2*)&up.y);
        r.x += pa.x; r.y += pa.y; r.z += pb.x; r.w += pb.y;
    }
    r.x = lrelu(r.x); r.y = lrelu(r.y); r.z = lrelu(r.z); r.w = lrelu(r.w);
    __half2 o0 = __floats2half2_rn(r.x, r.y);
    __half2 o1 = __floats2half2_rn(r.z, r.w);
    *(uint2*)&out[node * HH + lane * 4] = make_uint2(*(uint32_t*)&o0, *(uint32_t*)&o1);
}

// ---------------- mma helpers ----------------
__device__ __forceinline__ uint32_t smem_u32(const void* p) {
    uint32_t a;
    asm("{ .reg .u64 t; cvta.to.shared.u64 t, %1; cvt.u32.u64 %0, t; }" : "=r"(a) : "l"(p));
    return a;
}
__device__ __forceinline__ void cp16(uint32_t saddr, const void* g) {
    asm volatile("cp.async.cg.shared.global [%0], [%1], 16;" :: "r"(saddr), "l"(g));
}
__device__ __forceinline__ void ldsm_x4(uint32_t r[4], uint32_t addr) {
    asm volatile("ldmatrix.sync.aligned.m8n8.x4.shared.b16 {%0,%1,%2,%3}, [%4];"
                 : "=r"(r[0]), "=r"(r[1]), "=r"(r[2]), "=r"(r[3]) : "r"(addr));
}
__device__ __forceinline__ void mma_f16(float c[4], const uint32_t a[4], uint32_t b0, uint32_t b1) {
    asm volatile(
        "mma.sync.aligned.m16n8k16.row.col.f32.f16.f16.f32 "
        "{%0,%1,%2,%3}, {%4,%5,%6,%7}, {%8,%9}, {%0,%1,%2,%3};"
        : "+f"(c[0]), "+f"(c[1]), "+f"(c[2]), "+f"(c[3])
        : "r"(a[0]), "r"(a[1]), "r"(a[2]), "r"(a[3]), "r"(b0), "r"(b1));
}
__device__ __forceinline__ uint32_t pack2h(float v0, float v1) {
    __half2 hp = __floats2half2_rn(v0, v1);
    return *(uint32_t*)&hp;
}

// ---------------- 1-term MMA pass, warp tile 16x64 ----------------
template<int AO, int WO>
__device__ __forceinline__ void mma_pass1(
    uint32_t sb, uint32_t aoff_base, uint32_t axor, int acg,
    int wn, int bn_local, int bcg, float acc[8][4]) {
#pragma unroll
    for (int ks = 0; ks < 8; ks++) {
        const int kb = ks * 32;
        uint32_t ah[4];
        uint32_t a_addr = sb + aoff_base + (uint32_t)((kb + acg) ^ axor);
        ldsm_x4(ah, a_addr + AO);
#pragma unroll
        for (int p = 0; p < 4; p++) {
            const int nrow = wn * 64 + p * 16 + bn_local;
            uint32_t b_addr = sb + (uint32_t)(nrow * 256)
                            + (uint32_t)((kb + bcg) ^ ((nrow & 7) << 4));
            uint32_t bh[4];
            ldsm_x4(bh, b_addr + WO);
            mma_f16(acc[2 * p],     ah, bh[0], bh[1]);
            mma_f16(acc[2 * p + 1], ah, bh[2], bh[3]);
        }
    }
}

#define SA_A 0
#define SW_W 16384
#define GEMM_SMEM 49152

// ---------------- conv1: A fp32 -> fp16 convert prologue (occupancy-4 experiment) ----------------
__global__ void __launch_bounds__(256, 4) conv1_gemm(
    const float* __restrict__ A,
    const uint4* __restrict__ Wt,
    __half* __restrict__ C,
    int M) {
    extern __shared__ char smem[];
    const uint32_t sb = smem_u32(smem);
    const int tid = threadIdx.x;
    const int lane = tid & 31;
    const int wid = tid >> 5;
    const int wm = wid & 3;
    const int wn = wid >> 2;
    const int blockRow = blockIdx.x * 64;

#pragma unroll
    for (int i = 0; i < 8; i++) {
        int c = tid + i * 256;
        int n = c >> 4;
        int kb = (c & 15) * 16;
        uint32_t off = (uint32_t)(n * 256) + (uint32_t)(kb ^ ((n & 7) << 4));
        cp16(sb + SW_W + off, &Wt[c]);
    }
    asm volatile("cp.async.commit_group;" ::: "memory");

#pragma unroll
    for (int i = 0; i < 8; i++) {
        int idx = tid + i * 256;
        int row = idx >> 5;
        int col = (idx & 31) * 4;
        int grow = blockRow + row;
        float4 v = make_float4(0.f, 0.f, 0.f, 0.f);
        if (grow < M) v = *(const float4*)&A[grow * HH + col];
        uint32_t h0 = pack2h(v.x, v.y);
        uint32_t h1 = pack2h(v.z, v.w);
        uint32_t off = (uint32_t)(row * 256) + (uint32_t)((col * 2) ^ ((row & 7) << 4));
        *(uint2*)(smem + SA_A + off) = make_uint2(h0, h1);
    }
    asm volatile("cp.async.wait_group 0;" ::: "memory");
    __syncthreads();

    float acc[8][4];
#pragma unroll
    for (int j = 0; j < 8; j++)
#pragma unroll
        for (int q = 0; q < 4; q++) acc[j][q] = 0.f;

    const int arow = wm * 16 + (lane & 15);
    const int acg = (lane >> 4) * 16;
    const uint32_t aoff_base = (uint32_t)(arow * 256);
    const uint32_t axor = (uint32_t)((arow & 7) << 4);
    const int bn_local = (lane & 7) + ((lane >> 4) & 1) * 8;
    const int bcg = ((lane >> 3) & 1) * 16;

    mma_pass1<SA_A, SW_W>(sb, aoff_base, axor, acg, wn, bn_local, bcg, acc);

    const int g = lane >> 2, t = lane & 3;
    int rr0 = blockRow + wm * 16 + g;
#pragma unroll
    for (int h = 0; h < 2; h++) {
        int row = rr0 + h * 8;
        if (row >= M) continue;
#pragma unroll
        for (int j = 0; j < 8; j++) {
            int col = wn * 64 + j * 8 + t * 2;
            *(__half2*)&C[row * HH + col] =
                __floats2half2_rn(acc[j][h * 2 + 0], acc[j][h * 2 + 1]);
        }
    }
}

// ---------------- conv2: A fp16 cp.async prologue; OUTPUT SCALED by dinv[row] ----------------
__global__ void __launch_bounds__(256, 3) conv2_gemm(
    const __half* __restrict__ A,        // h1 fp16
    const uint4* __restrict__ Wt,
    __half* __restrict__ C,              // (h1@Wc2)*dinv[row] fp16
    int M) {
    extern __shared__ char smem[];
    const uint32_t sb = smem_u32(smem);
    const int tid = threadIdx.x;
    const int lane = tid & 31;
    const int wid = tid >> 5;
    const int wm = wid & 3;
    const int wn = wid >> 2;
    const int blockRow = blockIdx.x * 64;

#pragma unroll
    for (int i = 0; i < 8; i++) {
        int c = tid + i * 256;
        int n = c >> 4;
        int kb = (c & 15) * 16;
        uint32_t off = (uint32_t)(n * 256) + (uint32_t)(kb ^ ((n & 7) << 4));
        cp16(sb + SW_W + off, &Wt[c]);
    }
#pragma unroll
    for (int i = 0; i < 4; i++) {
        int idx = tid + i * 256;
        int row = idx >> 4;
        int chunk = idx & 15;
        int grow = blockRow + row;
        uint32_t off = (uint32_t)(row * 256) + (uint32_t)((chunk * 16) ^ ((row & 7) << 4));
        if (grow < M) {
            cp16(sb + SA_A + off, &A[grow * HH + chunk * 8]);
        } else {
            *(uint4*)(smem + SA_A + off) = make_uint4(0, 0, 0, 0);
        }
    }
    asm volatile("cp.async.commit_group;" ::: "memory");
    asm volatile("cp.async.wait_group 0;" ::: "memory");
    __syncthreads();

    float acc[8][4];
#pragma unroll
    for (int j = 0; j < 8; j++)
#pragma unroll
        for (int q = 0; q < 4; q++) acc[j][q] = 0.f;

    const int arow = wm * 16 + (lane & 15);
    const int acg = (lane >> 4) * 16;
    const uint32_t aoff_base = (uint32_t)(arow * 256);
    const uint32_t axor = (uint32_t)((arow & 7) << 4);
    const int bn_local = (lane & 7) + ((lane >> 4) & 1) * 8;
    const int bcg = ((lane >> 3) & 1) * 16;

    mma_pass1<SA_A, SW_W>(sb, aoff_base, axor, acg, wn, bn_local, bcg, acc);

    const int g = lane >> 2, t = lane & 3;
    int rr0 = blockRow + wm * 16 + g;
#pragma unroll
    for (int h = 0; h < 2; h++) {
        int row = rr0 + h * 8;
        if (row >= M) continue;
        float sc = g_dinv[row];
#pragma unroll
        for (int j = 0; j < 8; j++) {
            int col = wn * 64 + j * 8 + t * 2;
            *(__half2*)&C[row * HH + col] =
                __floats2half2_rn(acc[j][h * 2 + 0] * sc, acc[j][h * 2 + 1] * sc);
        }
    }
}

// ---------------- 4-layer fused MLP: fp16 A via cp.async, fp16 resid ----------------
#define G_A 0
#define G_W 16384
#define G_SMEM 49152

struct MLP4Args {
    const uint4* w[4];
    const float* b[4];
};

__global__ void __launch_bounds__(256, 3) mlp4(
    const __half* __restrict__ A,     // h2 fp16 (also the residual)
    MLP4Args args,
    const float* __restrict__ gen,
    float* __restrict__ C,
    int M) {
    extern __shared__ char smem[];
    const uint32_t sb = smem_u32(smem);
    const int tid = threadIdx.x;
    const int lane = tid & 31;
    const int wid = tid >> 5;
    const int wm = wid & 3;
    const int wn = wid >> 2;
    const int blockRow = blockIdx.x * 64;

#pragma unroll
    for (int i = 0; i < 8; i++) {
        int c = tid + i * 256;
        int n = c >> 4;
        int kb = (c & 15) * 16;
        uint32_t off = (uint32_t)(n * 256) + (uint32_t)(kb ^ ((n & 7) << 4));
        cp16(sb + G_W + off, &args.w[0][c]);
    }
#pragma unroll
    for (int i = 0; i < 4; i++) {
        int idx = tid + i * 256;
        int row = idx >> 4;
        int chunk = idx & 15;
        int grow = blockRow + row;
        uint32_t off = (uint32_t)(row * 256) + (uint32_t)((chunk * 16) ^ ((row & 7) << 4));
        if (grow < M) {
            cp16(sb + G_A + off, &A[grow * HH + chunk * 8]);
        } else {
            *(uint4*)(smem + G_A + off) = make_uint4(0, 0, 0, 0);
        }
    }
    asm volatile("cp.async.commit_group;" ::: "memory");
    asm volatile("cp.async.wait_group 0;" ::: "memory");
    __syncthreads();

    const int arow = wm * 16 + (lane & 15);
    const int acg = (lane >> 4) * 16;
    const uint32_t aoff_base = (uint32_t)(arow * 256);
    const uint32_t axor = (uint32_t)((arow & 7) << 4);
    const int bn_local = (lane & 7) + ((lane >> 4) & 1) * 8;
    const int bcg = ((lane >> 3) & 1) * 16;
    const int g = lane >> 2, t = lane & 3;

    float acc[8][4];

#pragma unroll
    for (int layer = 0; layer < 4; layer++) {
#pragma unroll
        for (int j = 0; j < 8; j++)
#pragma unroll
            for (int q = 0; q < 4; q++) acc[j][q] = 0.f;
        mma_pass1<G_A, G_W>(sb, aoff_base, axor, acg, wn, bn_local, bcg, acc);
        __syncthreads();

        if (layer < 3) {
#pragma unroll
            for (int i = 0; i < 8; i++) {
                int c = tid + i * 256;
                int n = c >> 4;
                int kb = (c & 15) * 16;
                uint32_t off = (uint32_t)(n * 256) + (uint32_t)(kb ^ ((n & 7) << 4));
                cp16(sb + G_W + off, &args.w[layer + 1][c]);
            }
            asm volatile("cp.async.commit_group;" ::: "memory");
        }

        const float* bias = args.b[layer];
        if (layer == 3) {
#pragma unroll
            for (int h = 0; h < 2; h++) {
                int row = blockRow + wm * 16 + g + h * 8;
                if (row >= M) continue;
#pragma unroll
                for (int j = 0; j < 8; j++) {
                    int col = wn * 64 + j * 8 + t * 2;
                    float v0 = lrelu(acc[j][h * 2 + 0] + bias[col]);
                    float v1 = lrelu(acc[j][h * 2 + 1] + bias[col + 1]);
                    *(float2*)&C[row * HH + col] = make_float2(v0, v1);
                }
            }
        } else {
#pragma unroll
            for (int h = 0; h < 2; h++) {
                int lrow = wm * 16 + g + h * 8;
                int grow = blockRow + lrow;
#pragma unroll
                for (int j = 0; j < 8; j++) {
                    int col = wn * 64 + j * 8 + t * 2;
                    float v0 = acc[j][h * 2 + 0] + bias[col];
                    float v1 = acc[j][h * 2 + 1] + bias[col + 1];
                    if (layer == 1) {
                        if (grow < M) {
                            uint32_t hv = *(const uint32_t*)&A[grow * HH + col];
                            float2 rv = __half22float2(*(__half2*)&hv);
                            v0 += rv.x; v1 += rv.y;
                        }
                        v0 = lrelu(v0); v1 = lrelu(v1);
                        float2 gv = (grow < M) ? *(const float2*)&gen[grow * HH + col]
                                               : make_float2(0.f, 0.f);
                        v0 = 0.5f * v0 + 0.5f * gv.x;
                        v1 = 0.5f * v1 + 0.5f * gv.y;
                    } else {
                        v0 = lrelu(v0); v1 = lrelu(v1);
                    }
                    uint32_t off = (uint32_t)(lrow * 256)
                                 + (uint32_t)((col * 2) ^ ((lrow & 7) << 4));
                    *(uint32_t*)(smem + G_A + off) = pack2h(v0, v1);
                }
            }
            asm volatile("cp.async.wait_group 0;" ::: "memory");
            __syncthreads();
        }
    }
}

// ---------------- launch ----------------
extern "C" void kernel_launch(void* const* d_in, const int* in_sizes, int n_in,
                              void* d_out, int out_size) {
    const float* x   = (const float*)d_in[0];
    const int*   ei  = (const int*)d_in[1];
    const float* gen = (const float*)d_in[2];
    const float* Wc1 = (const float*)d_in[3];
    const float* bc1 = (const float*)d_in[4];
    const float* Wc2 = (const float*)d_in[5];
    const float* bc2 = (const float*)d_in[6];
    const float* Wm1 = (const float*)d_in[7];
    const float* bm1 = (const float*)d_in[8];
    const float* Wm2 = (const float*)d_in[9];
    const float* bm2 = (const float*)d_in[10];
    const float* Wp1 = (const float*)d_in[11];
    const float* bp1 = (const float*)d_in[12];
    const float* Wp2 = (const float*)d_in[13];
    const float* bp2 = (const float*)d_in[14];

    const int* src = ei;
    const int* dst = ei + EE;

    float *bufA, *bufB, *bufC;
    __half* wh;
    int* cntp;
    cudaGetSymbolAddress((void**)&bufA, g_bufA);
    cudaGetSymbolAddress((void**)&bufB, g_bufB);
    cudaGetSymbolAddress((void**)&bufC, g_bufC);
    cudaGetSymbolAddress((void**)&wh, g_wh);
    cudaGetSymbolAddress((void**)&cntp, g_cnt);

    static bool s_init = false;
    static cudaStream_t s_side;
    static cudaEvent_t ev_fork, ev_join;
    if (!s_init) {
        cudaStreamCreateWithFlags(&s_side, cudaStreamNonBlocking);
        cudaEventCreateWithFlags(&ev_fork, cudaEventDisableTiming);
        cudaEventCreateWithFlags(&ev_join, cudaEventDisableTiming);
        cudaFuncSetAttribute(conv1_gemm, cudaFuncAttributeMaxDynamicSharedMemorySize, GEMM_SMEM);
        cudaFuncSetAttribute(conv2_gemm, cudaFuncAttributeMaxDynamicSharedMemorySize, GEMM_SMEM);
        cudaFuncSetAttribute(mlp4, cudaFuncAttributeMaxDynamicSharedMemorySize, G_SMEM);
        s_init = true;
    }

    const int gE4 = (EE / 4 + 255) / 256;
    const int gN = (NN + 255) / 256;
    const int gGat = (NN * 32 + 255) / 256;   // warp per node
    const int gG = (NN + 63) / 64;            // M=64 tiles

    const uint4* w4 = (const uint4*)wh;
    const int WSTEP = HH * HH / 8;
    __half* h1raw = (__half*)bufA;   // x@Wc1 (fp16)
    __half* h1buf = (__half*)bufB;   // leaky(gcn1) fp16
    __half* h2raw = (__half*)bufA;   // (h1@Wc2)*dinv (scaled) — reuses bufA
    __half* h2buf = (__half*)bufC;   // h2 fp16

    WPtrs wp;
    wp.p[0] = Wc1; wp.p[1] = Wc2; wp.p[2] = Wm1;
    wp.p[3] = Wm2; wp.p[4] = Wp1; wp.p[5] = Wp2;
    dim3 wgrid((HH * HH + 255) / 256, 6);

    // fork: CSR build + dinv on side stream (hidden under wconv + conv1)
    cudaMemsetAsync(cntp, 0, NN * sizeof(int));
    cudaEventRecord(ev_fork, 0);
    cudaStreamWaitEvent(s_side, ev_fork, 0);
    fill_kernel<<<gE4, 256, 0, s_side>>>(src, dst);
    dinv_kernel<<<gN, 256, 0, s_side>>>();
    cudaEventRecord(ev_join, s_side);

    // main: weights + conv1 GEMM (independent of CSR)
    wconv_all<<<wgrid, 256>>>(wp);
    conv1_gemm<<<gG, 256, GEMM_SMEM>>>(x, w4, h1raw, NN);

    // join: gather needs CSR + dinv
    cudaStreamWaitEvent(0, ev_join, 0);
    gather_kernel<false><<<gGat, 256>>>(h1raw, bc1, nullptr, h1buf);   // h1 fp16

    conv2_gemm<<<gG, 256, GEMM_SMEM>>>(h1buf, w4 + WSTEP, h2raw, NN);  // scaled by dinv[row]
    gather_kernel<true><<<gGat, 256>>>(h2raw, bc2, h1buf, h2buf);      // h2 fp16 (no per-edge dinv)

    MLP4Args ma;
    ma.w[0] = w4 + 2 * WSTEP; ma.b[0] = bm1;
    ma.w[1] = w4 + 3 * WSTEP; ma.b[1] = bm2;
    ma.w[2] = w4 + 4 * WSTEP; ma.b[2] = bp1;
    ma.w[3] = w4 + 5 * WSTEP; ma.b[3] = bp2;
    mlp4<<<gG, 256, G_SMEM>>>(h2buf, ma, gen, (float*)d_out, NN);
}